// round 1
// baseline (speedup 1.0000x reference)
#include <cuda_runtime.h>
#include <cuda_bf16.h>

#define WW    7
#define BX    32
#define BY    4
#define TX    (BX + 6)   // 38
#define TY    (BY + 6)   // 10
#define IND   384
#define OUTD  377
#define BATCH 32
#define NTHREADS 128

__global__ __launch_bounds__(NTHREADS)
void dct_conv_kernel(const float* __restrict__ X, float* __restrict__ out)
{
    __shared__ float Dsh[49];            // D[k][n] = 2*cos(pi*k*(2n+1)/14)
    __shared__ float Xs[TY][TX];         // input tile
    __shared__ float Vs[7][BY][TX];      // vertical DCT pass

    const int tid = threadIdx.x;
    const int x0  = blockIdx.x * BX;
    const int y0  = blockIdx.y * BY;
    const int b   = blockIdx.z;

    if (tid < 49) {
        int k = tid / 7, n = tid % 7;
        Dsh[tid] = 2.0f * cospif((float)(k * (2 * n + 1)) / 14.0f);
    }

    // ---- stage input tile (clamped, out-of-range values are never used) ----
    const float* Xb = X + (long long)b * IND * IND;
    #pragma unroll
    for (int i = tid; i < TY * TX; i += NTHREADS) {
        int r  = i / TX, c = i % TX;
        int gr = y0 + r, gc = x0 + c;
        float v = 0.0f;
        if (gr < IND && gc < IND) v = __ldg(Xb + gr * IND + gc);
        Xs[r][c] = v;
    }
    __syncthreads();

    // ---- vertical DCT pass: Vs[k][ty][xx] = sum_m D[k][m] * Xs[ty+m][xx] ----
    #pragma unroll
    for (int i = tid; i < 7 * BY * TX; i += NTHREADS) {
        int k   = i / (BY * TX);
        int rem = i % (BY * TX);
        int ty  = rem / TX;
        int xx  = rem % TX;
        float s = 0.0f;
        #pragma unroll
        for (int m = 0; m < 7; m++)
            s = fmaf(Dsh[k * 7 + m], Xs[ty + m][xx], s);
        Vs[k][ty][xx] = s;
    }
    __syncthreads();

    // ---- horizontal DCT pass: one pixel per thread ----
    const int tx = tid & 31;
    const int ty = tid >> 5;
    const int x  = x0 + tx;
    const int y  = y0 + ty;
    if (x >= OUTD || y >= OUTD) return;

    float res[49];
    #pragma unroll
    for (int k = 0; k < 7; k++) {
        float a0 = 0.f, a1 = 0.f, a2 = 0.f, a3 = 0.f, a4 = 0.f, a5 = 0.f, a6 = 0.f;
        #pragma unroll
        for (int n = 0; n < 7; n++) {
            float v = Vs[k][ty][tx + n];
            a0 = fmaf(Dsh[0 * 7 + n], v, a0);
            a1 = fmaf(Dsh[1 * 7 + n], v, a1);
            a2 = fmaf(Dsh[2 * 7 + n], v, a2);
            a3 = fmaf(Dsh[3 * 7 + n], v, a3);
            a4 = fmaf(Dsh[4 * 7 + n], v, a4);
            a5 = fmaf(Dsh[5 * 7 + n], v, a5);
            a6 = fmaf(Dsh[6 * 7 + n], v, a6);
        }
        res[k * 7 + 0] = a0; res[k * 7 + 1] = a1; res[k * 7 + 2] = a2;
        res[k * 7 + 3] = a3; res[k * 7 + 4] = a4; res[k * 7 + 5] = a5;
        res[k * 7 + 6] = a6;
    }

    // ---- writes: zf (channel 0), hf (channels 1..48, contiguous per pixel) ----
    const long long pix = ((long long)b * OUTD + y) * OUTD + x;
    out[pix] = res[0];

    const long long ZF_SIZE = (long long)BATCH * OUTD * OUTD;
    float4* hf = (float4*)(out + ZF_SIZE + pix * 48);
    #pragma unroll
    for (int j = 0; j < 12; j++) {
        hf[j] = make_float4(res[1 + 4 * j], res[2 + 4 * j],
                            res[3 + 4 * j], res[4 + 4 * j]);
    }
}

extern "C" void kernel_launch(void* const* d_in, const int* in_sizes, int n_in,
                              void* d_out, int out_size)
{
    const float* X = (const float*)d_in[0];
    float* out = (float*)d_out;

    dim3 grid((OUTD + BX - 1) / BX,   // 12
              (OUTD + BY - 1) / BY,   // 95
              BATCH);                 // 32
    dct_conv_kernel<<<grid, NTHREADS>>>(X, out);
}

// round 2
// speedup vs baseline: 1.4790x; 1.4790x over previous
#include <cuda_runtime.h>
#include <cuda_bf16.h>

#define BX    32
#define BY    4
#define TX    (BX + 6)   // 38
#define IND   384
#define OUTD  377
#define BATCH 32
#define NTHREADS 128
#define PSTRIDE 49       // words per pixel in Osh (odd -> conflict-free STS)

__global__ __launch_bounds__(NTHREADS)
void dct_conv_kernel(const float* __restrict__ X, float* __restrict__ out)
{
    __shared__ float Dsh[49];                 // D[k][n] = 2*cos(pi*k*(2n+1)/14)
    __shared__ float Xs[BY + 6][TX];          // input tile
    __shared__ float Vs[7][BY][TX];           // vertical DCT pass
    __shared__ float Osh[BY][BX * PSTRIDE];   // staged outputs: [row][pix*49 + ch]

    const int tid = threadIdx.x;
    const int x0  = blockIdx.x * BX;
    const int y0  = blockIdx.y * BY;
    const int b   = blockIdx.z;

    if (tid < 49) {
        int k = tid / 7, n = tid % 7;
        Dsh[tid] = 2.0f * cospif((float)(k * (2 * n + 1)) / 14.0f);
    }

    // ---- stage input tile (clamped; OOB values only feed invalid pixels) ----
    const float* Xb = X + (long long)b * IND * IND;
    #pragma unroll
    for (int i = tid; i < (BY + 6) * TX; i += NTHREADS) {
        int r  = i / TX, c = i % TX;
        int gr = y0 + r, gc = x0 + c;
        float v = 0.0f;
        if (gr < IND && gc < IND) v = __ldg(Xb + gr * IND + gc);
        Xs[r][c] = v;
    }
    __syncthreads();

    // ---- vertical DCT pass: Vs[k][ty][xx] = sum_m D[k][m] * Xs[ty+m][xx] ----
    #pragma unroll
    for (int i = tid; i < 7 * BY * TX; i += NTHREADS) {
        int k   = i / (BY * TX);
        int rem = i % (BY * TX);
        int ty  = rem / TX;
        int xx  = rem % TX;
        float s = 0.0f;
        #pragma unroll
        for (int m = 0; m < 7; m++)
            s = fmaf(Dsh[k * 7 + m], Xs[ty + m][xx], s);
        Vs[k][ty][xx] = s;
    }
    __syncthreads();

    // ---- horizontal DCT pass: one pixel per thread, results staged to Osh ----
    {
        const int tx = tid & 31;
        const int ty = tid >> 5;
        float* op = &Osh[ty][tx * PSTRIDE];
        #pragma unroll
        for (int k = 0; k < 7; k++) {
            float a0 = 0.f, a1 = 0.f, a2 = 0.f, a3 = 0.f, a4 = 0.f, a5 = 0.f, a6 = 0.f;
            #pragma unroll
            for (int n = 0; n < 7; n++) {
                float v = Vs[k][ty][tx + n];
                a0 = fmaf(Dsh[0 * 7 + n], v, a0);
                a1 = fmaf(Dsh[1 * 7 + n], v, a1);
                a2 = fmaf(Dsh[2 * 7 + n], v, a2);
                a3 = fmaf(Dsh[3 * 7 + n], v, a3);
                a4 = fmaf(Dsh[4 * 7 + n], v, a4);
                a5 = fmaf(Dsh[5 * 7 + n], v, a5);
                a6 = fmaf(Dsh[6 * 7 + n], v, a6);
            }
            op[k * 7 + 0] = a0; op[k * 7 + 1] = a1; op[k * 7 + 2] = a2;
            op[k * 7 + 3] = a3; op[k * 7 + 4] = a4; op[k * 7 + 5] = a5;
            op[k * 7 + 6] = a6;
        }
    }
    __syncthreads();

    // ---- coalesced epilogue ----
    const int nvx = min(BX, OUTD - x0);          // valid pixels in x (32 or 25)
    const long long ZF_SIZE = (long long)BATCH * OUTD * OUTD;

    // zf: channel 0 of each pixel (coalesced 128B per warp)
    {
        const int tx = tid & 31;
        const int ty = tid >> 5;
        const int x  = x0 + tx;
        const int y  = y0 + ty;
        if (x < OUTD && y < OUTD)
            out[((long long)b * OUTD + y) * OUTD + x] = Osh[ty][tx * PSTRIDE];
    }

    // hf: channels 1..48, contiguous run of nvx*48 floats per row.
    #pragma unroll
    for (int r = 0; r < BY; r++) {
        const int y = y0 + r;
        if (y >= OUTD) break;
        const long long pix0 = ((long long)b * OUTD + y) * OUTD + x0;
        float4* dst = (float4*)(out + ZF_SIZE + pix0 * 48);
        const int nf4 = nvx * 12;                // 48 floats = 12 float4 per pixel
        const float* src = Osh[r];
        for (int f = tid; f < nf4; f += NTHREADS) {
            int pixel = f / 12;
            int c     = (f % 12) * 4;
            int sa    = pixel * PSTRIDE + 1 + c; // +1 skips channel 0
            dst[f] = make_float4(src[sa], src[sa + 1], src[sa + 2], src[sa + 3]);
        }
    }
}

extern "C" void kernel_launch(void* const* d_in, const int* in_sizes, int n_in,
                              void* d_out, int out_size)
{
    const float* X = (const float*)d_in[0];
    float* out = (float*)d_out;

    dim3 grid((OUTD + BX - 1) / BX,   // 12
              (OUTD + BY - 1) / BY,   // 95
              BATCH);                 // 32
    dct_conv_kernel<<<grid, NTHREADS>>>(X, out);
}

// round 3
// speedup vs baseline: 1.8041x; 1.2198x over previous
#include <cuda_runtime.h>
#include <cuda_bf16.h>

#define BX    32
#define BY    4
#define TX    38            // BX + 6
#define TYR   10            // BY + 6
#define IND   384
#define OUTD  377
#define BATCH 32
#define NT    128
#define OST   129           // Osh pixel stride: ≡1 mod 32 -> conflict-light

__global__ __launch_bounds__(NT)
void dct_conv_kernel(const float* __restrict__ X, float* __restrict__ out)
{
    __shared__ float Dsh[49];          // D[k][n] = 2*cos(pi*k*(2n+1)/14)
    __shared__ float Xs[TYR][TX];      // input tile
    __shared__ float Vs[7][BY][TX];    // vertical DCT pass
    __shared__ float Osh[49][OST];     // channel-major staged outputs

    const int tid = threadIdx.x;
    const int x0  = blockIdx.x * BX;
    const int y0  = blockIdx.y * BY;
    const int b   = blockIdx.z;

    if (tid < 49) {
        int k = tid / 7, n = tid % 7;
        Dsh[tid] = 2.0f * cospif((float)(k * (2 * n + 1)) / 14.0f);
    }

    // ---- stage input tile (clamped; OOB values only feed invalid pixels) ----
    const float* Xb = X + (size_t)b * IND * IND;
    #pragma unroll
    for (int i = tid; i < TYR * TX; i += NT) {
        int r  = i / TX, c = i - r * TX;
        int gr = y0 + r, gc = x0 + c;
        Xs[r][c] = (gr < IND && gc < IND) ? __ldg(Xb + gr * IND + gc) : 0.0f;
    }
    __syncthreads();

    // ---- vertical pass, register-blocked: task per (ty, xx), 7 loads -> 7 outs
    for (int i = tid; i < BY * TX; i += NT) {
        int ty = i / TX, xx = i - ty * TX;
        float xr[7];
        #pragma unroll
        for (int m = 0; m < 7; m++) xr[m] = Xs[ty + m][xx];
        #pragma unroll
        for (int k = 0; k < 7; k++) {
            float s = 0.0f;
            #pragma unroll
            for (int m = 0; m < 7; m++)
                s = fmaf(Dsh[k * 7 + m], xr[m], s);
            Vs[k][ty][xx] = s;
        }
    }
    __syncthreads();

    // ---- horizontal pass: thread = pixel (tid 0..127), channel-major STS ----
    {
        const int ty = tid >> 5;
        const int tx = tid & 31;
        #pragma unroll
        for (int k = 0; k < 7; k++) {
            float v[7];
            #pragma unroll
            for (int n = 0; n < 7; n++) v[n] = Vs[k][ty][tx + n];

            #pragma unroll
            for (int i = 0; i < 7; i++) {
                float a = 0.0f;
                #pragma unroll
                for (int n = 0; n < 7; n++)
                    a = fmaf(Dsh[i * 7 + n], v[n], a);
                Osh[k * 7 + i][tid] = a;   // lanes consecutive -> conflict-free
            }
        }
    }
    __syncthreads();

    // ---- epilogue ----
    const int nvx = min(BX, OUTD - x0);
    const long long ZF = (long long)BATCH * OUTD * OUTD;

    // zf: channel 0, fully coalesced
    {
        int r = tid >> 5;
        int x = x0 + (tid & 31);
        int y = y0 + r;
        if (x < OUTD && y < OUTD)
            out[((size_t)b * OUTD + y) * OUTD + x] = Osh[0][tid];
    }

    // hf: channels 1..48, pixel-major float4 stream per row
    #pragma unroll
    for (int r = 0; r < BY; r++) {
        const int y = y0 + r;
        if (y >= OUTD) break;
        float4* dst = (float4*)(out + ZF +
                                (((size_t)b * OUTD + y) * OUTD + x0) * 48);
        #pragma unroll
        for (int j = 0; j < 3; j++) {
            int g  = tid + j * NT;      // 0..383 : f4 index within row
            int pl = g / 12;            // pixel within row (0..31)
            int c  = g - pl * 12;       // f4 slot within pixel (0..11)
            if (pl < nvx) {
                int sp = (r << 5) + pl; // pixel index in Osh
                int ch = 1 + (c << 2);  // first channel of this f4
                dst[g] = make_float4(Osh[ch][sp],     Osh[ch + 1][sp],
                                     Osh[ch + 2][sp], Osh[ch + 3][sp]);
            }
        }
    }
}

extern "C" void kernel_launch(void* const* d_in, const int* in_sizes, int n_in,
                              void* d_out, int out_size)
{
    const float* X = (const float*)d_in[0];
    float* out = (float*)d_out;

    dim3 grid((OUTD + BX - 1) / BX,   // 12
              (OUTD + BY - 1) / BY,   // 95
              BATCH);                 // 32
    dct_conv_kernel<<<grid, NT>>>(X, out);
}

// round 4
// speedup vs baseline: 1.8267x; 1.0125x over previous
#include <cuda_runtime.h>
#include <cuda_bf16.h>

#define BX    32
#define BY    4
#define TX    38            // BX + 6
#define TYR   10            // BY + 6
#define IND   384
#define OUTD  377
#define BATCH 32
#define NT    128
#define OP    129           // Osh4 pixel-dim stride (f4 units)

__global__ __launch_bounds__(NT)
void dct_conv_kernel(const float* __restrict__ X, float* __restrict__ out)
{
    __shared__ float  Dsh[49];           // D[k][n] = 2*cos(pi*k*(2n+1)/14)
    __shared__ float  Xs[TYR][TX];       // input tile
    __shared__ float  Vs[7][BY][TX];     // vertical DCT pass
    __shared__ float  Oz[NT];            // zf channel per pixel
    __shared__ float4 Osh4[12 * OP];     // hf channels: [c][pixel], f4-packed

    const int tid = threadIdx.x;
    const int x0  = blockIdx.x * BX;
    const int y0  = blockIdx.y * BY;
    const int b   = blockIdx.z;

    if (tid < 49) {
        int k = tid / 7, n = tid % 7;
        Dsh[tid] = 2.0f * cospif((float)(k * (2 * n + 1)) / 14.0f);
    }

    // ---- stage input tile (clamped; OOB values only feed invalid pixels) ----
    const float* Xb = X + (size_t)b * IND * IND;
    #pragma unroll
    for (int i = tid; i < TYR * TX; i += NT) {
        int r  = i / TX, c = i - r * TX;
        int gr = y0 + r, gc = x0 + c;
        Xs[r][c] = (gr < IND && gc < IND) ? __ldg(Xb + gr * IND + gc) : 0.0f;
    }
    __syncthreads();

    // ---- vertical pass, register-blocked ----
    for (int i = tid; i < BY * TX; i += NT) {
        int ty = i / TX, xx = i - ty * TX;
        float xr[7];
        #pragma unroll
        for (int m = 0; m < 7; m++) xr[m] = Xs[ty + m][xx];
        #pragma unroll
        for (int k = 0; k < 7; k++) {
            float s = 0.0f;
            #pragma unroll
            for (int m = 0; m < 7; m++)
                s = fmaf(Dsh[k * 7 + m], xr[m], s);
            Vs[k][ty][xx] = s;
        }
    }
    __syncthreads();

    // ---- horizontal pass: thread = pixel; rolling f4 pack, STS.128 ----
    {
        const int ty = tid >> 5;
        const int tx = tid & 31;
        float b0 = 0.f, b1 = 0.f, b2 = 0.f;
        #pragma unroll
        for (int k = 0; k < 7; k++) {
            float v[7];
            #pragma unroll
            for (int n = 0; n < 7; n++) v[n] = Vs[k][ty][tx + n];

            #pragma unroll
            for (int i = 0; i < 7; i++) {
                float a = 0.0f;
                #pragma unroll
                for (int n = 0; n < 7; n++)
                    a = fmaf(Dsh[i * 7 + n], v[n], a);

                const int ch = k * 7 + i;          // compile-time constant
                if (ch == 0) {
                    Oz[tid] = a;
                } else {
                    const int pos = (ch - 1) & 3;  // compile-time constant
                    if      (pos == 0) b0 = a;
                    else if (pos == 1) b1 = a;
                    else if (pos == 2) b2 = a;
                    else {
                        const int c = (ch - 4) >> 2;     // 0..11
                        Osh4[c * OP + tid] = make_float4(b0, b1, b2, a);
                    }
                }
            }
        }
    }
    __syncthreads();

    // ---- epilogue ----
    const int nvx = min(BX, OUTD - x0);
    const long long ZF = (long long)BATCH * OUTD * OUTD;

    // zf: channel 0, fully coalesced
    {
        int x = x0 + (tid & 31);
        int y = y0 + (tid >> 5);
        if (x < OUTD && y < OUTD)
            out[((size_t)b * OUTD + y) * OUTD + x] = Oz[tid];
    }

    // hf: per row, LDS.128 from Osh4 -> aligned STG.128 stream
    #pragma unroll
    for (int r = 0; r < BY; r++) {
        const int y = y0 + r;
        if (y >= OUTD) break;
        float4* dst = (float4*)(out + ZF +
                                (((size_t)b * OUTD + y) * OUTD + x0) * 48);
        #pragma unroll
        for (int j = 0; j < 3; j++) {
            int g  = tid + j * NT;        // f4 index within row: 0..383
            int pl = g / 12;              // pixel within row
            int c  = g - pl * 12;         // f4 slot within pixel
            if (pl < nvx)
                dst[g] = Osh4[c * OP + (r << 5) + pl];
        }
    }
}

extern "C" void kernel_launch(void* const* d_in, const int* in_sizes, int n_in,
                              void* d_out, int out_size)
{
    const float* X = (const float*)d_in[0];
    float* out = (float*)d_out;

    dim3 grid((OUTD + BX - 1) / BX,   // 12
              (OUTD + BY - 1) / BY,   // 95
              BATCH);                 // 32
    dct_conv_kernel<<<grid, NT>>>(X, out);
}

// round 5
// speedup vs baseline: 2.2106x; 1.2102x over previous
#include <cuda_runtime.h>
#include <cuda_bf16.h>

#define BX    32
#define BY    4
#define TX    38            // BX + 6
#define TYR   10            // BY + 6
#define IND   384
#define OUTD  377
#define BATCH 32
#define NT    128
#define OP    129           // Osh4 pixel-dim stride (f4 units)

// D[k][n] = 2*cos(pi*k*(2n+1)/14), exact compile-time constants -> FFMA-imm
__device__ static constexpr float DC[7][7] = {
  { 2.0f, 2.0f, 2.0f, 2.0f, 2.0f, 2.0f, 2.0f },
  { 1.9498558243636472f,  1.5636629649360596f,  0.8677674782351162f, 0.0f,
   -0.8677674782351162f, -1.5636629649360596f, -1.9498558243636472f },
  { 1.8019377358048383f,  0.4450418679126288f, -1.2469796037174672f, -2.0f,
   -1.2469796037174672f,  0.4450418679126288f,  1.8019377358048383f },
  { 1.5636629649360596f, -0.8677674782351162f, -1.9498558243636472f, 0.0f,
    1.9498558243636472f,  0.8677674782351162f, -1.5636629649360596f },
  { 1.2469796037174672f, -1.8019377358048383f, -0.4450418679126288f, 2.0f,
   -0.4450418679126288f, -1.8019377358048383f,  1.2469796037174672f },
  { 0.8677674782351162f, -1.9498558243636472f,  1.5636629649360596f, 0.0f,
   -1.5636629649360596f,  1.9498558243636472f, -0.8677674782351162f },
  { 0.4450418679126288f, -1.2469796037174672f,  1.8019377358048383f, -2.0f,
    1.8019377358048383f, -1.2469796037174672f,  0.4450418679126288f }
};

__global__ __launch_bounds__(NT)
void dct_conv_kernel(const float* __restrict__ X, float* __restrict__ out)
{
    __shared__ float  Xs[TYR][TX];       // input tile
    __shared__ float  Vs[7][BY][TX];     // vertical DCT pass
    __shared__ float  Oz[NT];            // zf channel per pixel
    __shared__ float4 Osh4[12 * OP];     // hf channels: [c][pixel], f4-packed

    const int tid = threadIdx.x;
    const int x0  = blockIdx.x * BX;
    const int y0  = blockIdx.y * BY;
    const int b   = blockIdx.z;

    // ---- stage input tile (clamped; OOB values only feed invalid pixels) ----
    const float* Xb = X + (size_t)b * IND * IND;
    #pragma unroll
    for (int i = tid; i < TYR * TX; i += NT) {
        int r  = i / TX, c = i - r * TX;
        int gr = y0 + r, gc = x0 + c;
        Xs[r][c] = (gr < IND && gc < IND) ? __ldg(Xb + gr * IND + gc) : 0.0f;
    }
    __syncthreads();

    // ---- vertical pass (butterfly + immediate coefficients) ----
    for (int i = tid; i < BY * TX; i += NT) {
        int ty = i / TX, xx = i - ty * TX;
        float x[7];
        #pragma unroll
        for (int m = 0; m < 7; m++) x[m] = Xs[ty + m][xx];
        float sx[3], dx[3];
        #pragma unroll
        for (int m = 0; m < 3; m++) { sx[m] = x[m] + x[6 - m]; dx[m] = x[m] - x[6 - m]; }

        #pragma unroll
        for (int k = 0; k < 7; k++) {
            float s;
            if ((k & 1) == 0) {
                s = DC[k][3] * x[3];
                #pragma unroll
                for (int m = 0; m < 3; m++) s = fmaf(DC[k][m], sx[m], s);
            } else {
                s = DC[k][0] * dx[0];
                s = fmaf(DC[k][1], dx[1], s);
                s = fmaf(DC[k][2], dx[2], s);
            }
            Vs[k][ty][xx] = s;
        }
    }
    __syncthreads();

    // ---- horizontal pass: thread = pixel; butterfly; rolling f4 pack ----
    {
        const int ty = tid >> 5;
        const int tx = tid & 31;
        float b0 = 0.f, b1 = 0.f, b2 = 0.f;
        #pragma unroll
        for (int k = 0; k < 7; k++) {
            float v[7];
            #pragma unroll
            for (int n = 0; n < 7; n++) v[n] = Vs[k][ty][tx + n];
            float sv[3], dv[3];
            #pragma unroll
            for (int n = 0; n < 3; n++) { sv[n] = v[n] + v[6 - n]; dv[n] = v[n] - v[6 - n]; }

            #pragma unroll
            for (int i = 0; i < 7; i++) {
                float a;
                if ((i & 1) == 0) {
                    a = DC[i][3] * v[3];
                    #pragma unroll
                    for (int n = 0; n < 3; n++) a = fmaf(DC[i][n], sv[n], a);
                } else {
                    a = DC[i][0] * dv[0];
                    a = fmaf(DC[i][1], dv[1], a);
                    a = fmaf(DC[i][2], dv[2], a);
                }

                const int ch = k * 7 + i;          // compile-time constant
                if (ch == 0) {
                    Oz[tid] = a;
                } else {
                    const int pos = (ch - 1) & 3;  // compile-time constant
                    if      (pos == 0) b0 = a;
                    else if (pos == 1) b1 = a;
                    else if (pos == 2) b2 = a;
                    else {
                        const int c = (ch - 4) >> 2;     // 0..11
                        Osh4[c * OP + tid] = make_float4(b0, b1, b2, a);
                    }
                }
            }
        }
    }
    __syncthreads();

    // ---- epilogue ----
    const int nvx = min(BX, OUTD - x0);
    const long long ZF = (long long)BATCH * OUTD * OUTD;

    // zf: channel 0, fully coalesced
    {
        int x = x0 + (tid & 31);
        int y = y0 + (tid >> 5);
        if (x < OUTD && y < OUTD)
            out[((size_t)b * OUTD + y) * OUTD + x] = Oz[tid];
    }

    // hf: per row, LDS.128 from Osh4 -> aligned STG.128 stream
    #pragma unroll
    for (int r = 0; r < BY; r++) {
        const int y = y0 + r;
        if (y >= OUTD) break;
        float4* dst = (float4*)(out + ZF +
                                (((size_t)b * OUTD + y) * OUTD + x0) * 48);
        #pragma unroll
        for (int j = 0; j < 3; j++) {
            int g  = tid + j * NT;        // f4 index within row: 0..383
            int pl = g / 12;              // pixel within row
            int c  = g - pl * 12;         // f4 slot within pixel
            if (pl < nvx)
                dst[g] = Osh4[c * OP + (r << 5) + pl];
        }
    }
}

extern "C" void kernel_launch(void* const* d_in, const int* in_sizes, int n_in,
                              void* d_out, int out_size)
{
    const float* X = (const float*)d_in[0];
    float* out = (float*)d_out;

    dim3 grid((OUTD + BX - 1) / BX,   // 12
              (OUTD + BY - 1) / BY,   // 95
              BATCH);                 // 32
    dct_conv_kernel<<<grid, NT>>>(X, out);
}

// round 6
// speedup vs baseline: 2.4260x; 1.0974x over previous
#include <cuda_runtime.h>
#include <cuda_bf16.h>

#define BX    32
#define BY    4
#define TX    38            // BX + 6
#define TYR   10            // BY + 6
#define IND   384
#define OUTD  377
#define BATCH 32
#define NT    128
#define SP    65            // Osh4 pixel-dim stride (f4 units), 2 rows + pad

// D[k][n] = 2*cos(pi*k*(2n+1)/14), compile-time constants -> FFMA-imm
__device__ static constexpr float DC[7][7] = {
  { 2.0f, 2.0f, 2.0f, 2.0f, 2.0f, 2.0f, 2.0f },
  { 1.9498558243636472f,  1.5636629649360596f,  0.8677674782351162f, 0.0f,
   -0.8677674782351162f, -1.5636629649360596f, -1.9498558243636472f },
  { 1.8019377358048383f,  0.4450418679126288f, -1.2469796037174672f, -2.0f,
   -1.2469796037174672f,  0.4450418679126288f,  1.8019377358048383f },
  { 1.5636629649360596f, -0.8677674782351162f, -1.9498558243636472f, 0.0f,
    1.9498558243636472f,  0.8677674782351162f, -1.5636629649360596f },
  { 1.2469796037174672f, -1.8019377358048383f, -0.4450418679126288f, 2.0f,
   -0.4450418679126288f, -1.8019377358048383f,  1.2469796037174672f },
  { 0.8677674782351162f, -1.9498558243636472f,  1.5636629649360596f, 0.0f,
   -1.5636629649360596f,  1.9498558243636472f, -0.8677674782351162f },
  { 0.4450418679126288f, -1.2469796037174672f,  1.8019377358048383f, -2.0f,
    1.8019377358048383f, -1.2469796037174672f,  0.4450418679126288f }
};

__global__ __launch_bounds__(NT, 9)
void dct_conv_kernel(const float* __restrict__ X, float* __restrict__ out)
{
    __shared__ float  Xs[TYR][TX];       // input tile
    __shared__ float  Vs[7][BY][TX];     // vertical DCT pass
    __shared__ float4 Osh4[12 * SP];     // hf staging for a 2-row group

    const int tid  = threadIdx.x;
    const int w    = tid >> 5;
    const int lane = tid & 31;
    const int x0   = blockIdx.x * BX;
    const int y0   = blockIdx.y * BY;
    const int b    = blockIdx.z;

    const int nvx = min(BX, OUTD - x0);
    const long long ZF = (long long)BATCH * OUTD * OUTD;

    // ---- stage input tile (clamped; OOB values only feed invalid pixels) ----
    const float* Xb = X + (size_t)b * IND * IND;
    #pragma unroll
    for (int i = tid; i < TYR * TX; i += NT) {
        int r  = i / TX, c = i - r * TX;
        int gr = y0 + r, gc = x0 + c;
        Xs[r][c] = (gr < IND && gc < IND) ? __ldg(Xb + gr * IND + gc) : 0.0f;
    }
    __syncthreads();

    // ---- vertical pass (butterfly + immediate coefficients) ----
    for (int i = tid; i < BY * TX; i += NT) {
        int ty = i / TX, xx = i - ty * TX;
        float x[7];
        #pragma unroll
        for (int m = 0; m < 7; m++) x[m] = Xs[ty + m][xx];
        float sx[3], dx[3];
        #pragma unroll
        for (int m = 0; m < 3; m++) { sx[m] = x[m] + x[6 - m]; dx[m] = x[m] - x[6 - m]; }

        #pragma unroll
        for (int k = 0; k < 7; k++) {
            float s;
            if ((k & 1) == 0) {
                s = DC[k][3] * x[3];
                #pragma unroll
                for (int m = 0; m < 3; m++) s = fmaf(DC[k][m], sx[m], s);
            } else {
                s = DC[k][0] * dx[0];
                s = fmaf(DC[k][1], dx[1], s);
                s = fmaf(DC[k][2], dx[2], s);
            }
            Vs[k][ty][xx] = s;
        }
    }
    __syncthreads();

    // ---- horizontal pass for one row, staged into 2-row buffer ----
    auto horiz_row = [&](int row, int slot) {
        float b0 = 0.f, b1 = 0.f, b2 = 0.f;
        const int sbase = slot * 32 + lane;
        #pragma unroll
        for (int k = 0; k < 7; k++) {
            float v[7];
            #pragma unroll
            for (int n = 0; n < 7; n++) v[n] = Vs[k][row][lane + n];
            float sv[3], dv[3];
            #pragma unroll
            for (int n = 0; n < 3; n++) { sv[n] = v[n] + v[6 - n]; dv[n] = v[n] - v[6 - n]; }

            #pragma unroll
            for (int i = 0; i < 7; i++) {
                float a;
                if ((i & 1) == 0) {
                    a = DC[i][3] * v[3];
                    #pragma unroll
                    for (int n = 0; n < 3; n++) a = fmaf(DC[i][n], sv[n], a);
                } else {
                    a = DC[i][0] * dv[0];
                    a = fmaf(DC[i][1], dv[1], a);
                    a = fmaf(DC[i][2], dv[2], a);
                }

                const int ch = k * 7 + i;            // compile-time constant
                if (ch == 0) {
                    int x = x0 + lane, y = y0 + row;
                    if (x < OUTD && y < OUTD)
                        __stcs(&out[((size_t)b * OUTD + y) * OUTD + x], a);
                } else {
                    const int pos = (ch - 1) & 3;    // compile-time constant
                    if      (pos == 0) b0 = a;
                    else if (pos == 1) b1 = a;
                    else if (pos == 2) b2 = a;
                    else Osh4[((ch - 4) >> 2) * SP + sbase] = make_float4(b0, b1, b2, a);
                }
            }
        }
    };

    // ---- drain one 2-row group: contiguous STG.128 per row ----
    auto drain = [&](int phase) {
        #pragma unroll
        for (int j = 0; j < 6; j++) {
            int g  = tid + j * NT;        // 0..767
            int rr = g / 384;
            int h  = g - rr * 384;
            int pl = h / 12;
            int c  = h - pl * 12;
            int y  = y0 + phase * 2 + rr;
            if (y < OUTD && pl < nvx) {
                float4* dst = (float4*)(out + ZF +
                              (((size_t)b * OUTD + y) * OUTD + x0) * 48);
                __stcs(&dst[pl * 12 + c], Osh4[c * SP + rr * 32 + pl]);
            }
        }
    };

    // phase 0: rows 0,1 computed by warps 0,1
    if (w < 2) horiz_row(w, w);
    __syncthreads();
    drain(0);
    __syncthreads();

    // phase 1: rows 2,3 computed by warps 2,3
    if (w >= 2) horiz_row(w, w - 2);
    __syncthreads();
    drain(1);
}

extern "C" void kernel_launch(void* const* d_in, const int* in_sizes, int n_in,
                              void* d_out, int out_size)
{
    const float* X = (const float*)d_in[0];
    float* out = (float*)d_out;

    dim3 grid((OUTD + BX - 1) / BX,   // 12
              (OUTD + BY - 1) / BY,   // 95
              BATCH);                 // 32
    dct_conv_kernel<<<grid, NT>>>(X, out);
}